// round 17
// baseline (speedup 1.0000x reference)
#include <cuda_runtime.h>
#include <cuda_bf16.h>
#include <cstdint>

// Soft-label distillation transform:
//   per row i: S = sum_j logits[i,j]; t = logits[i,label_i];
//   s = 0.95 / (1 + S - 2t)
//   out[i, j]     = s * logits[i,j]      (j != label)
//   out[i, label] = s*t + (1 - s*S)
//
// B=4096 rows, C=32000 cols, fp32 in/out, labels int32.
//
// History: R8 = 161us (DRAM 81.5%): SMEM-staged, refill burst after the
// drain — read stream idles ~1000cyc/row while registers die via STS.
// R11/R14: interleaving refills into the drain REGRESSED (69.4%/78.8%)
// — batched bursts win; the register-WAR is the root cause of the idle.
// R15: missing <cstdint> compile fail. R16/R17 = fixed, unchanged.
//
// Design: break the WAR with cp.async (LDGSTS). Row lives in registers
// r[8]; the refill for row n+1 goes GMEM->SMEM via cp.async issued at
// the TOP of row n (no registers consumed -> full-row latency cover,
// reads stream from cycle 0 of every row). After the store burst:
// wait_group + 8x LDS.128 pulls the landed row into registers
// (thread-private slots -> no barrier needed; each thread reads only
// bytes its own cp.asyncs wrote). LDS copy == R8's STS drain in
// crossbar cost, but it no longer gates the DRAM read stream.
//
// 2 barriers/row; sS/sT parity-buffered (slot p rewritten only after
// both barriers of iter n+1, postdating all register captures of iter
// n). t published by unique owner (tid = lvec & 1023, k = lvec >> 10).
// Overwrite hazard (iter-n LDS vs iter-n+1 cp.async, same thread/addr):
// LDS is 29cyc fixed-latency and issues first in program order;
// cp.async data lands >= ~250cyc after issue — safe margin.
// HBM traffic at the 1.05 GB floor. __stcs on output (write-once).

#define BATCH 4096
#define NUM_CLASSES 32000
#define NVEC (NUM_CLASSES / 4)   // 8000 float4 per row
#define NTHREADS 1024
#define ALPHA 0.95f

__device__ __forceinline__ void cp_async16(unsigned int smem_addr,
                                           const void* gptr)
{
    asm volatile("cp.async.cg.shared.global [%0], [%1], 16;\n"
                 :: "r"(smem_addr), "l"(gptr));
}
__device__ __forceinline__ void cp_async_commit()
{
    asm volatile("cp.async.commit_group;\n" ::: "memory");
}
__device__ __forceinline__ void cp_async_wait_all()
{
    asm volatile("cp.async.wait_group 0;\n" ::: "memory");
}

__global__ __launch_bounds__(NTHREADS, 1)
void distill_kernel(const float* __restrict__ logits,
                    const int* __restrict__ labels,
                    float* __restrict__ out)
{
    extern __shared__ float4 buf4[];               // 8000 float4 = 128 KB
    __shared__ float warpsum[32];
    __shared__ float sS[2];                        // parity-buffered scalars
    __shared__ float sT[2];

    const int  tid    = threadIdx.x;
    const bool lastok = (tid + 7 * NTHREADS) < NVEC;   // k=7 chunk valid?
    const long stride = (long)gridDim.x * NVEC;        // float4s per row-step

    float4 r[8];

    // Per-thread pointers (thread offset folded in).
    const float4* in4  = reinterpret_cast<const float4*>(logits)
                         + (size_t)blockIdx.x * NVEC + tid;
    float4*       out4 = reinterpret_cast<float4*>(out)
                         + (size_t)blockIdx.x * NVEC + tid;

    // Thread-private smem slot base (byte address), chunk k at +k*NTHREADS*16.
    const unsigned int sbase =
        (unsigned int)__cvta_generic_to_shared(buf4) + (unsigned int)tid * 16u;

    // Prologue: plain LDG for the first row; label for it.
    #pragma unroll
    for (int k = 0; k < 7; k++) r[k] = __ldcs(in4 + k * NTHREADS);
    if (lastok)                r[7] = __ldcs(in4 + 7 * NTHREADS);
    const float4* nin4 = in4 + stride;             // gmem src for refills
    int label = __ldg(&labels[blockIdx.x]);

    int p = 0;                                     // row parity
    for (int b = blockIdx.x; b < BATCH; b += gridDim.x, p ^= 1) {
        const int  nb    = b + gridDim.x;
        const int  lvec  = label >> 2;
        const int  llane = label & 3;
        const bool more  = (nb < BATCH);

        // 1. Row-top refill: cp.async burst for row n+1 (GMEM->SMEM, no
        //    registers). Full-row latency cover; reads stream immediately.
        if (more) {
            #pragma unroll
            for (int k = 0; k < 8; k++) {
                if (k == 7 && !lastok) break;
                cp_async16(sbase + (unsigned int)(k * NTHREADS) * 16u,
                           nin4 + k * NTHREADS);
            }
            cp_async_commit();
        }

        // 2. Sum from registers; unique owner publishes t.
        float lsum = 0.0f;
        #pragma unroll
        for (int k = 0; k < 8; k++) {
            if (k == 7 && !lastok) break;
            float4 v = r[k];
            lsum += (v.x + v.y) + (v.z + v.w);
            if (tid + k * NTHREADS == lvec) {      // constant-k unrolled test
                sT[p] = (llane == 0) ? v.x : (llane == 1) ? v.y
                      : (llane == 2) ? v.z : v.w;
            }
        }

        // 3. Block reduction of S (2 barriers).
        #pragma unroll
        for (int o = 16; o > 0; o >>= 1)
            lsum += __shfl_xor_sync(0xFFFFFFFFu, lsum, o);
        if ((tid & 31) == 0) warpsum[tid >> 5] = lsum;
        __syncthreads();                           // bar1: warpsum + sT
        if (tid < 32) {
            float v = warpsum[tid];
            #pragma unroll
            for (int o = 16; o > 0; o >>= 1)
                v += __shfl_xor_sync(0xFFFFFFFFu, v, o);
            if (tid == 0) sS[p] = v;
        }
        __syncthreads();                           // bar2: sS

        const float S    = sS[p];
        const float t    = sT[p];
        const float s    = ALPHA / (1.0f + S - 2.0f * t);
        const float corr = 1.0f - s * S;

        if (more) label = __ldg(&labels[nb]);      // next label, covered here

        // 4. Store burst: scale registers, patch label, stream out.
        #pragma unroll
        for (int k = 0; k < 8; k++) {
            if (k == 7 && !lastok) break;
            const int i = tid + k * NTHREADS;
            float4 v = r[k];
            v.x *= s; v.y *= s; v.z *= s; v.w *= s;
            if (i == lvec) {                       // ISETP + @P FADD
                float* vf = reinterpret_cast<float*>(&v);
                vf[llane] += corr;
            }
            __stcs(out4 + k * NTHREADS, v);
        }

        // 5. Land the refill: wait own cp.asyncs, copy SMEM->registers.
        //    Thread-private slots -> no cross-thread barrier needed.
        if (more) {
            cp_async_wait_all();
            #pragma unroll
            for (int k = 0; k < 8; k++) {
                if (k == 7 && !lastok) break;
                r[k] = buf4[tid + k * NTHREADS];   // LDS.128, conflict-free
            }
        }
        nin4 += stride;
        out4 += stride;
    }
}

extern "C" void kernel_launch(void* const* d_in, const int* in_sizes, int n_in,
                              void* d_out, int out_size)
{
    const float* logits = (const float*)d_in[0];
    const int*   labels = (const int*)d_in[1];
    float*       out    = (float*)d_out;

    const int smem_bytes = NVEC * sizeof(float4);  // 128 KB landing buffer
    (void)cudaFuncSetAttribute(distill_kernel,
                               cudaFuncAttributeMaxDynamicSharedMemorySize,
                               smem_bytes);

    // Persistent grid: exactly #SMs (152 on GB300). Never more — at
    // 1 CTA/SM occupancy a surplus CTA would serialize behind a full loop.
    int dev = 0, nsm = 148;
    (void)cudaGetDevice(&dev);
    (void)cudaDeviceGetAttribute(&nsm, cudaDevAttrMultiProcessorCount, dev);
    int grid = nsm < BATCH ? nsm : BATCH;

    distill_kernel<<<grid, NTHREADS, smem_bytes>>>(logits, labels, out);
}